// round 6
// baseline (speedup 1.0000x reference)
#include <cuda_runtime.h>
#include <math.h>

#define N_NODES  100000
#define N_EDGES  400000
#define N_GRAPHS 256
#define HID      256
#define LAYERS   3
#define EPSF     1e-5f

// ---------------- scratch (device globals; no allocations allowed) ----------
__device__ float g_h  [(long)N_NODES * HID];
__device__ float g_z  [(long)N_NODES * HID];
__device__ float g_t  [(long)N_NODES * HID];
__device__ float g_e  [(long)N_EDGES * HID];
__device__ float g_e1 [(long)N_EDGES * HID];
__device__ float g_Wc [4 * HID];
__device__ float g_bc [HID];
__device__ float g_bioC[HID];
__device__ float g_cnt[N_GRAPHS];
__device__ float g_S1 [N_GRAPHS * HID];
__device__ float g_S2 [N_GRAPHS * HID];
__device__ float g_pool[N_GRAPHS * HID];

// ---------------- small utility kernels -------------------------------------
__global__ void zero_f(float* __restrict__ p, int n) {
    int i = blockIdx.x * blockDim.x + threadIdx.x;
    int stride = gridDim.x * blockDim.x;
    for (; i < n; i += stride) p[i] = 0.f;
}

__global__ void count_k(const int* __restrict__ batch, float* __restrict__ cnt) {
    int i = blockIdx.x * blockDim.x + threadIdx.x;
    if (i < N_NODES) atomicAdd(&cnt[batch[i]], 1.f);
}

// h[i] = node_emb_W[x[i]]
__global__ void embed_k(const int* __restrict__ x, const float* __restrict__ emb,
                        float* __restrict__ h) {
    int id = blockIdx.x * blockDim.x + threadIdx.x;      // N_NODES*64
    int r = id >> 6, c4 = id & 63;
    const float4* e4 = (const float4*)emb;
    ((float4*)h)[id] = e4[x[r] * 64 + c4];
}

// Precompute: Wc = We@W1, bc = be@W1 + b1, bioC = mean_bio @ head_W1[HID:]
__global__ void prep_k(const float* __restrict__ We, const float* __restrict__ be,
                       const float* __restrict__ W1, const float* __restrict__ b1,
                       const float* __restrict__ bio, const float* __restrict__ hW1,
                       float* __restrict__ Wc, float* __restrict__ bc,
                       float* __restrict__ bioC) {
    int n = threadIdx.x;  // 256 threads, 1 block
    float a0 = 0, a1 = 0, a2 = 0, a3 = 0, ab = 0;
    for (int j = 0; j < HID; j++) {
        float w = W1[j * HID + n];
        a0 += We[0 * HID + j] * w;
        a1 += We[1 * HID + j] * w;
        a2 += We[2 * HID + j] * w;
        a3 += We[3 * HID + j] * w;
        ab += be[j] * w;
    }
    float av = 0;
    for (int j = 0; j < 512; j++) av += bio[j] * hW1[(HID + j) * HID + n];
    Wc[0 * HID + n] = a0; Wc[1 * HID + n] = a1;
    Wc[2 * HID + n] = a2; Wc[3 * HID + n] = a3;
    bc[n] = ab + b1[n];
    bioC[n] = av;
}

// e1 = relu(edge_attr @ Wc + bc)   (K=4 GEMM, fully fused)
__global__ void edge_k4(const float* __restrict__ attr, const float* __restrict__ Wc,
                        const float* __restrict__ bc, float* __restrict__ e1) {
    int id = blockIdx.x * blockDim.x + threadIdx.x;      // N_EDGES*64
    int eid = id >> 6, c4 = id & 63;
    float4 a = *(const float4*)(attr + (long)eid * 4);
    const float4* W4 = (const float4*)Wc;
    float4 w0 = W4[0 * 64 + c4], w1 = W4[64 + c4], w2 = W4[128 + c4], w3 = W4[192 + c4];
    float4 bb = ((const float4*)bc)[c4];
    float4 v;
    v.x = fmaxf(a.x * w0.x + a.y * w1.x + a.z * w2.x + a.w * w3.x + bb.x, 0.f);
    v.y = fmaxf(a.x * w0.y + a.y * w1.y + a.z * w2.y + a.w * w3.y + bb.y, 0.f);
    v.z = fmaxf(a.x * w0.z + a.y * w1.z + a.z * w2.z + a.w * w3.z + bb.z, 0.f);
    v.w = fmaxf(a.x * w0.w + a.y * w1.w + a.z * w2.w + a.w * w3.w + bb.w, 0.f);
    ((float4*)e1)[id] = v;
}

// z = (1 + conv_eps[l]) * h
__global__ void zinit_k(float* __restrict__ z, const float* __restrict__ h,
                        const float* __restrict__ eps, int l) {
    int id = blockIdx.x * blockDim.x + threadIdx.x;      // N_NODES*64
    float s = 1.f + eps[l];
    float4 v = ((const float4*)h)[id];
    v.x *= s; v.y *= s; v.z *= s; v.w *= s;
    ((float4*)z)[id] = v;
}

// z[dst] += relu(h[src] + e)   (scatter)
__global__ void scatter_k(const float* __restrict__ e, const float* __restrict__ h,
                          float* __restrict__ z, const int* __restrict__ src,
                          const int* __restrict__ dst) {
    int id = blockIdx.x * blockDim.x + threadIdx.x;      // N_EDGES*64
    int eid = id >> 6, c = (id & 63) << 2;
    int s = __ldg(src + eid), d = __ldg(dst + eid);
    float4 ev = *(const float4*)(e + (long)eid * HID + c);
    float4 hv = *(const float4*)(h + (long)s * HID + c);
    float* zp = z + (long)d * HID + c;
    atomicAdd(zp + 0, fmaxf(hv.x + ev.x, 0.f));
    atomicAdd(zp + 1, fmaxf(hv.y + ev.y, 0.f));
    atomicAdd(zp + 2, fmaxf(hv.z + ev.z, 0.f));
    atomicAdd(zp + 3, fmaxf(hv.w + ev.w, 0.f));
}

// ---------------- per-graph stats (batch is sorted -> run-length flush) -----
#define RPT 16
__global__ void stats_k(const float* __restrict__ h, const int* __restrict__ batch,
                        float* __restrict__ S1, float* __restrict__ S2) {
    int id = blockIdx.x * blockDim.x + threadIdx.x;
    if (id >= (N_NODES / RPT) * 64) return;
    int c = (id & 63) << 2;
    int r0 = (id >> 6) * RPT;
    float4 s1 = make_float4(0, 0, 0, 0), s2 = make_float4(0, 0, 0, 0);
    int cur = __ldg(batch + r0);
    for (int i = 0; i < RPT; i++) {
        int r = r0 + i;
        int g = __ldg(batch + r);
        if (g != cur) {
            float* p1 = S1 + cur * HID + c;
            float* p2 = S2 + cur * HID + c;
            atomicAdd(p1 + 0, s1.x); atomicAdd(p1 + 1, s1.y);
            atomicAdd(p1 + 2, s1.z); atomicAdd(p1 + 3, s1.w);
            atomicAdd(p2 + 0, s2.x); atomicAdd(p2 + 1, s2.y);
            atomicAdd(p2 + 2, s2.z); atomicAdd(p2 + 3, s2.w);
            s1 = make_float4(0, 0, 0, 0); s2 = make_float4(0, 0, 0, 0);
            cur = g;
        }
        float4 v = *(const float4*)(h + (long)r * HID + c);
        s1.x += v.x; s1.y += v.y; s1.z += v.z; s1.w += v.w;
        s2.x += v.x * v.x; s2.y += v.y * v.y; s2.z += v.z * v.z; s2.w += v.w * v.w;
    }
    float* p1 = S1 + cur * HID + c;
    float* p2 = S2 + cur * HID + c;
    atomicAdd(p1 + 0, s1.x); atomicAdd(p1 + 1, s1.y);
    atomicAdd(p1 + 2, s1.z); atomicAdd(p1 + 3, s1.w);
    atomicAdd(p2 + 0, s2.x); atomicAdd(p2 + 1, s2.y);
    atomicAdd(p2 + 2, s2.z); atomicAdd(p2 + 3, s2.w);
}

// Turn (S1,S2) into per-(g,n) affine coefs:  h_norm = A*h + B
// var = E[h^2] + m^2*(a^2 - 2a);  A = gamma*rsqrt(var+eps);  B = beta - A*a*m
__global__ void norm_fin_k(float* __restrict__ S1, float* __restrict__ S2,
                           const float* __restrict__ cnt,
                           const float* __restrict__ gamma,
                           const float* __restrict__ beta,
                           const float* __restrict__ alpha) {
    int id = blockIdx.x * blockDim.x + threadIdx.x;  // G*HID
    int g = id >> 8, n = id & 255;
    float c = fmaxf(cnt[g], 1.f);
    float m = S1[id] / c;
    float eh2 = S2[id] / c;
    float a = alpha[n];
    float var = eh2 + m * m * (a * a - 2.f * a);
    float A = gamma[n] * rsqrtf(var + EPSF);
    float B = beta[n] - A * a * m;
    S1[id] = A; S2[id] = B;
}

__global__ void norm_apply_k(float* __restrict__ h, const int* __restrict__ batch,
                             const float* __restrict__ S1, const float* __restrict__ S2) {
    int id = blockIdx.x * blockDim.x + threadIdx.x;  // N_NODES*64
    int r = id >> 6, c4 = id & 63;
    int g = __ldg(batch + r);
    float4 a = ((const float4*)S1)[g * 64 + c4];
    float4 b = ((const float4*)S2)[g * 64 + c4];
    float4 v = ((const float4*)h)[id];
    v.x = a.x * v.x + b.x; v.y = a.y * v.y + b.y;
    v.z = a.z * v.z + b.z; v.w = a.w * v.w + b.w;
    ((float4*)h)[id] = v;
}

__global__ void pool_fin_k(const float* __restrict__ S1, const float* __restrict__ cnt,
                           float* __restrict__ pool) {
    int id = blockIdx.x * blockDim.x + threadIdx.x;  // G*HID
    int g = id >> 8;
    pool[id] = S1[id] / fmaxf(cnt[g], 1.f);
}

// ---------------- SGEMM: C = epi(A[M,256] @ W[256,256] + bias) --------------
// EPI: 0 plain, 1 relu, 2 edge struct-scale
#define BM 128
#define BN 128
#define BK 8
#define ASTR 132

template <int EPI>
__global__ __launch_bounds__(256, 2)
void gemm_k256(const float* __restrict__ A, const float* __restrict__ W,
               const float* __restrict__ bias, float* __restrict__ C, int M,
               const float* __restrict__ eattr, const float* __restrict__ sscale) {
    __shared__ float As[2][BK * ASTR];
    __shared__ float Bs[2][BK * BN];
    const int tid = threadIdx.x;
    const int bm = blockIdx.y * BM;
    const int bn = blockIdx.x * BN;

    const int arow = tid >> 1;          // 0..127
    const int acol = (tid & 1) * 4;     // 0 or 4
    const int brow = tid >> 5;          // 0..7
    const int bcol = (tid & 31) * 4;    // 0..124
    const int m0 = (tid >> 4) * 8;
    const int n0 = (tid & 15) * 8;

    float acc[8][8];
#pragma unroll
    for (int i = 0; i < 8; i++)
#pragma unroll
        for (int j = 0; j < 8; j++) acc[i][j] = 0.f;

    float4 aldg, bldg;
    {
        int r = bm + arow;
        aldg = (r < M) ? *(const float4*)(A + (long)r * HID + acol)
                       : make_float4(0, 0, 0, 0);
        bldg = *(const float4*)(W + (long)brow * HID + bn + bcol);
        As[0][(acol + 0) * ASTR + arow] = aldg.x;
        As[0][(acol + 1) * ASTR + arow] = aldg.y;
        As[0][(acol + 2) * ASTR + arow] = aldg.z;
        As[0][(acol + 3) * ASTR + arow] = aldg.w;
        *(float4*)(&Bs[0][brow * BN + bcol]) = bldg;
    }
    __syncthreads();

    const int NCH = HID / BK;  // 32
    for (int kc = 0; kc < NCH; kc++) {
        int buf = kc & 1;
        if (kc + 1 < NCH) {
            int k0 = (kc + 1) * BK;
            int r = bm + arow;
            aldg = (r < M) ? *(const float4*)(A + (long)r * HID + k0 + acol)
                           : make_float4(0, 0, 0, 0);
            bldg = *(const float4*)(W + (long)(k0 + brow) * HID + bn + bcol);
        }
#pragma unroll
        for (int kk = 0; kk < BK; kk++) {
            float a[8], b[8];
            *(float4*)(a)     = *(const float4*)(&As[buf][kk * ASTR + m0]);
            *(float4*)(a + 4) = *(const float4*)(&As[buf][kk * ASTR + m0 + 4]);
            *(float4*)(b)     = *(const float4*)(&Bs[buf][kk * BN + n0]);
            *(float4*)(b + 4) = *(const float4*)(&Bs[buf][kk * BN + n0 + 4]);
#pragma unroll
            for (int i = 0; i < 8; i++)
#pragma unroll
                for (int j = 0; j < 8; j++) acc[i][j] += a[i] * b[j];
        }
        if (kc + 1 < NCH) {
            int nb = buf ^ 1;
            As[nb][(acol + 0) * ASTR + arow] = aldg.x;
            As[nb][(acol + 1) * ASTR + arow] = aldg.y;
            As[nb][(acol + 2) * ASTR + arow] = aldg.z;
            As[nb][(acol + 3) * ASTR + arow] = aldg.w;
            *(float4*)(&Bs[nb][brow * BN + bcol]) = bldg;
        }
        __syncthreads();
    }

    float bsv[8];
    *(float4*)(bsv)     = *(const float4*)(bias + bn + n0);
    *(float4*)(bsv + 4) = *(const float4*)(bias + bn + n0 + 4);
    float ss = 1.f;
    if (EPI == 2) ss = *sscale;

#pragma unroll
    for (int i = 0; i < 8; i++) {
        int row = bm + m0 + i;
        if (row < M) {
            float scale = 1.f;
            if (EPI == 2) scale = (__ldg(eattr + (long)row * 4 + 1) > 0.f) ? ss : 1.f;
            float o[8];
#pragma unroll
            for (int j = 0; j < 8; j++) {
                float v = acc[i][j] + bsv[j];
                if (EPI == 1) v = fmaxf(v, 0.f);
                if (EPI == 2) v *= scale;
                o[j] = v;
            }
            *(float4*)(C + (long)row * HID + bn + n0)     = *(float4*)(o);
            *(float4*)(C + (long)row * HID + bn + n0 + 4) = *(float4*)(o + 4);
        }
    }
}

// ---------------- head: out[g] = relu(pool@W1t + bioC + b1) @ W2 + b2 -------
__global__ void head_k(const float* __restrict__ pool, const float* __restrict__ W1,
                       const float* __restrict__ b1, const float* __restrict__ bioC,
                       const float* __restrict__ W2, const float* __restrict__ b2,
                       float* __restrict__ out) {
    __shared__ float srow[HID];
    __shared__ float sred[256];
    int g = blockIdx.x, t = threadIdx.x;
    srow[t] = pool[g * HID + t];
    __syncthreads();
    float acc = bioC[t] + b1[t];
#pragma unroll 8
    for (int k = 0; k < HID; k++) acc += srow[k] * W1[k * HID + t];
    acc = fmaxf(acc, 0.f);
    sred[t] = acc * W2[t];
    __syncthreads();
    for (int s = 128; s > 0; s >>= 1) {
        if (t < s) sred[t] += sred[t + s];
        __syncthreads();
    }
    if (t == 0) out[g] = sred[0] + b2[0];
}

// ---------------- launch -----------------------------------------------------
static float* sym(const void* s) {
    void* p = nullptr;
    cudaGetSymbolAddress(&p, s);
    return (float*)p;
}

extern "C" void kernel_launch(void* const* d_in, const int* in_sizes, int n_in,
                              void* d_out, int out_size) {
    const int*   x     = (const int*)  d_in[0];
    const int*   ei    = (const int*)  d_in[1];
    const float* eattr = (const float*)d_in[2];
    const int*   batch = (const int*)  d_in[3];
    const float* nemb  = (const float*)d_in[4];
    const float* eeW   = (const float*)d_in[5];
    const float* eeb   = (const float*)d_in[6];
    const float* emW1  = (const float*)d_in[7];
    const float* emb1  = (const float*)d_in[8];
    const float* emW2  = (const float*)d_in[9];
    const float* emb2  = (const float*)d_in[10];
    const float* sscale= (const float*)d_in[11];
    const float* cW1   = (const float*)d_in[12];
    const float* cb1   = (const float*)d_in[13];
    const float* cW2   = (const float*)d_in[14];
    const float* cb2   = (const float*)d_in[15];
    const float* ceps  = (const float*)d_in[16];
    const float* gamma = (const float*)d_in[17];
    const float* beta  = (const float*)d_in[18];
    const float* alpha = (const float*)d_in[19];
    const float* bio   = (const float*)d_in[20];
    const float* hW1   = (const float*)d_in[21];
    const float* hb1   = (const float*)d_in[22];
    const float* hW2   = (const float*)d_in[23];
    const float* hb2   = (const float*)d_in[24];
    float* out = (float*)d_out;

    const int* src = ei;
    const int* dst = ei + N_EDGES;

    float *ph = sym(g_h), *pz = sym(g_z), *pt = sym(g_t);
    float *pe = sym(g_e), *pe1 = sym(g_e1);
    float *pWc = sym(g_Wc), *pbc = sym(g_bc), *pbio = sym(g_bioC);
    float *pcnt = sym(g_cnt), *pS1 = sym(g_S1), *pS2 = sym(g_S2);
    float *ppool = sym(g_pool);

    // precompute collapsed edge weights + bio constant
    prep_k<<<1, 256>>>(eeW, eeb, emW1, emb1, bio, hW1, pWc, pbc, pbio);

    // node counts per graph
    zero_f<<<1, 256>>>(pcnt, N_GRAPHS);
    count_k<<<(N_NODES + 255) / 256, 256>>>(batch, pcnt);

    // node embedding
    embed_k<<<(N_NODES * 64) / 256, 256>>>(x, nemb, ph);

    // edge features: e1 = relu(attr@Wc+bc); e = (e1@W2+b2)*struct_scale
    edge_k4<<<(N_EDGES * 64) / 256, 256>>>(eattr, pWc, pbc, pe1);
    gemm_k256<2><<<dim3(2, N_EDGES / BM), 256>>>(pe1, emW2, emb2, pe, N_EDGES,
                                                 eattr, sscale);

    const int gyN = (N_NODES + BM - 1) / BM;
    for (int l = 0; l < LAYERS; l++) {
        zinit_k<<<(N_NODES * 64) / 256, 256>>>(pz, ph, ceps, l);
        scatter_k<<<(N_EDGES * 64) / 256, 256>>>(pe, ph, pz, src, dst);
        gemm_k256<1><<<dim3(2, gyN), 256>>>(pz, cW1 + (long)l * HID * HID,
                                            cb1 + l * HID, pt, N_NODES,
                                            nullptr, nullptr);
        gemm_k256<0><<<dim3(2, gyN), 256>>>(pt, cW2 + (long)l * HID * HID,
                                            cb2 + l * HID, ph, N_NODES,
                                            nullptr, nullptr);
        // GraphNorm
        zero_f<<<256, 256>>>(pS1, N_GRAPHS * HID);
        zero_f<<<256, 256>>>(pS2, N_GRAPHS * HID);
        stats_k<<<((N_NODES / RPT) * 64 + 255) / 256, 256>>>(ph, batch, pS1, pS2);
        norm_fin_k<<<N_GRAPHS * HID / 256, 256>>>(pS1, pS2, pcnt,
                                                  gamma + l * HID, beta + l * HID,
                                                  alpha + l * HID);
        norm_apply_k<<<(N_NODES * 64) / 256, 256>>>(ph, batch, pS1, pS2);
    }

    // global mean pool
    zero_f<<<256, 256>>>(pS1, N_GRAPHS * HID);
    zero_f<<<256, 256>>>(pS2, N_GRAPHS * HID);
    stats_k<<<((N_NODES / RPT) * 64 + 255) / 256, 256>>>(ph, batch, pS1, pS2);
    pool_fin_k<<<N_GRAPHS * HID / 256, 256>>>(pS1, pcnt, ppool);

    // head
    head_k<<<N_GRAPHS, 256>>>(ppool, hW1, hb1, pbio, hW2, hb2, out);

    (void)in_sizes; (void)n_in; (void)out_size;
}

// round 7
// speedup vs baseline: 1.0074x; 1.0074x over previous
#include <cuda_runtime.h>
#include <math.h>

#define N_NODES  100000
#define N_EDGES  400000
#define N_GRAPHS 256
#define HID      256
#define LAYERS   3
#define EPSF     1e-5f

// ---------------- scratch (device globals; no allocations allowed) ----------
__device__ float g_h  [(long)N_NODES * HID];
__device__ float g_z  [(long)N_NODES * HID];
__device__ float g_t  [(long)N_NODES * HID];
__device__ float g_e  [(long)N_EDGES * HID];
__device__ float g_e1 [(long)N_EDGES * HID];
__device__ float g_Wc [4 * HID];
__device__ float g_bc [HID];
__device__ float g_bioC[HID];
__device__ float g_cnt[N_GRAPHS];
__device__ float g_S1 [N_GRAPHS * HID];
__device__ float g_S2 [N_GRAPHS * HID];
__device__ float g_pool[N_GRAPHS * HID];

// ---------------- small utility kernels -------------------------------------
__global__ void zero_f(float* __restrict__ p, int n) {
    int i = blockIdx.x * blockDim.x + threadIdx.x;
    int stride = gridDim.x * blockDim.x;
    for (; i < n; i += stride) p[i] = 0.f;
}

__global__ void count_k(const int* __restrict__ batch, float* __restrict__ cnt) {
    int i = blockIdx.x * blockDim.x + threadIdx.x;
    if (i < N_NODES) atomicAdd(&cnt[batch[i]], 1.f);
}

// h[i] = node_emb_W[x[i]]
__global__ void embed_k(const int* __restrict__ x, const float* __restrict__ emb,
                        float* __restrict__ h) {
    int id = blockIdx.x * blockDim.x + threadIdx.x;      // N_NODES*64
    int r = id >> 6, c4 = id & 63;
    const float4* e4 = (const float4*)emb;
    ((float4*)h)[id] = e4[x[r] * 64 + c4];
}

// Precompute: Wc = We@W1, bc = be@W1 + b1, bioC = mean_bio @ head_W1[HID:]
__global__ void prep_k(const float* __restrict__ We, const float* __restrict__ be,
                       const float* __restrict__ W1, const float* __restrict__ b1,
                       const float* __restrict__ bio, const float* __restrict__ hW1,
                       float* __restrict__ Wc, float* __restrict__ bc,
                       float* __restrict__ bioC) {
    int n = threadIdx.x;  // 256 threads, 1 block
    float a0 = 0, a1 = 0, a2 = 0, a3 = 0, ab = 0;
    for (int j = 0; j < HID; j++) {
        float w = W1[j * HID + n];
        a0 += We[0 * HID + j] * w;
        a1 += We[1 * HID + j] * w;
        a2 += We[2 * HID + j] * w;
        a3 += We[3 * HID + j] * w;
        ab += be[j] * w;
    }
    float av = 0;
    for (int j = 0; j < 512; j++) av += bio[j] * hW1[(HID + j) * HID + n];
    Wc[0 * HID + n] = a0; Wc[1 * HID + n] = a1;
    Wc[2 * HID + n] = a2; Wc[3 * HID + n] = a3;
    bc[n] = ab + b1[n];
    bioC[n] = av;
}

// e1 = relu(edge_attr @ Wc + bc)   (K=4 GEMM, fully fused)
__global__ void edge_k4(const float* __restrict__ attr, const float* __restrict__ Wc,
                        const float* __restrict__ bc, float* __restrict__ e1) {
    int id = blockIdx.x * blockDim.x + threadIdx.x;      // N_EDGES*64
    int eid = id >> 6, c4 = id & 63;
    float4 a = *(const float4*)(attr + (long)eid * 4);
    const float4* W4 = (const float4*)Wc;
    float4 w0 = W4[0 * 64 + c4], w1 = W4[64 + c4], w2 = W4[128 + c4], w3 = W4[192 + c4];
    float4 bb = ((const float4*)bc)[c4];
    float4 v;
    v.x = fmaxf(a.x * w0.x + a.y * w1.x + a.z * w2.x + a.w * w3.x + bb.x, 0.f);
    v.y = fmaxf(a.x * w0.y + a.y * w1.y + a.z * w2.y + a.w * w3.y + bb.y, 0.f);
    v.z = fmaxf(a.x * w0.z + a.y * w1.z + a.z * w2.z + a.w * w3.z + bb.z, 0.f);
    v.w = fmaxf(a.x * w0.w + a.y * w1.w + a.z * w2.w + a.w * w3.w + bb.w, 0.f);
    ((float4*)e1)[id] = v;
}

// z = (1 + conv_eps[l]) * h
__global__ void zinit_k(float* __restrict__ z, const float* __restrict__ h,
                        const float* __restrict__ eps, int l) {
    int id = blockIdx.x * blockDim.x + threadIdx.x;      // N_NODES*64
    float s = 1.f + eps[l];
    float4 v = ((const float4*)h)[id];
    v.x *= s; v.y *= s; v.z *= s; v.w *= s;
    ((float4*)z)[id] = v;
}

// z[dst] += relu(h[src] + e)   (scatter)
__global__ void scatter_k(const float* __restrict__ e, const float* __restrict__ h,
                          float* __restrict__ z, const int* __restrict__ src,
                          const int* __restrict__ dst) {
    int id = blockIdx.x * blockDim.x + threadIdx.x;      // N_EDGES*64
    int eid = id >> 6, c = (id & 63) << 2;
    int s = __ldg(src + eid), d = __ldg(dst + eid);
    float4 ev = *(const float4*)(e + (long)eid * HID + c);
    float4 hv = *(const float4*)(h + (long)s * HID + c);
    float* zp = z + (long)d * HID + c;
    atomicAdd(zp + 0, fmaxf(hv.x + ev.x, 0.f));
    atomicAdd(zp + 1, fmaxf(hv.y + ev.y, 0.f));
    atomicAdd(zp + 2, fmaxf(hv.z + ev.z, 0.f));
    atomicAdd(zp + 3, fmaxf(hv.w + ev.w, 0.f));
}

// ---------------- per-graph stats (batch is sorted -> run-length flush) -----
#define RPT 16
__global__ void stats_k(const float* __restrict__ h, const int* __restrict__ batch,
                        float* __restrict__ S1, float* __restrict__ S2) {
    int id = blockIdx.x * blockDim.x + threadIdx.x;
    if (id >= (N_NODES / RPT) * 64) return;
    int c = (id & 63) << 2;
    int r0 = (id >> 6) * RPT;
    float4 s1 = make_float4(0, 0, 0, 0), s2 = make_float4(0, 0, 0, 0);
    int cur = __ldg(batch + r0);
    for (int i = 0; i < RPT; i++) {
        int r = r0 + i;
        int g = __ldg(batch + r);
        if (g != cur) {
            float* p1 = S1 + cur * HID + c;
            float* p2 = S2 + cur * HID + c;
            atomicAdd(p1 + 0, s1.x); atomicAdd(p1 + 1, s1.y);
            atomicAdd(p1 + 2, s1.z); atomicAdd(p1 + 3, s1.w);
            atomicAdd(p2 + 0, s2.x); atomicAdd(p2 + 1, s2.y);
            atomicAdd(p2 + 2, s2.z); atomicAdd(p2 + 3, s2.w);
            s1 = make_float4(0, 0, 0, 0); s2 = make_float4(0, 0, 0, 0);
            cur = g;
        }
        float4 v = *(const float4*)(h + (long)r * HID + c);
        s1.x += v.x; s1.y += v.y; s1.z += v.z; s1.w += v.w;
        s2.x += v.x * v.x; s2.y += v.y * v.y; s2.z += v.z * v.z; s2.w += v.w * v.w;
    }
    float* p1 = S1 + cur * HID + c;
    float* p2 = S2 + cur * HID + c;
    atomicAdd(p1 + 0, s1.x); atomicAdd(p1 + 1, s1.y);
    atomicAdd(p1 + 2, s1.z); atomicAdd(p1 + 3, s1.w);
    atomicAdd(p2 + 0, s2.x); atomicAdd(p2 + 1, s2.y);
    atomicAdd(p2 + 2, s2.z); atomicAdd(p2 + 3, s2.w);
}

// Turn (S1,S2) into per-(g,n) affine coefs:  h_norm = A*h + B
// var = E[h^2] + m^2*(a^2 - 2a);  A = gamma*rsqrt(var+eps);  B = beta - A*a*m
__global__ void norm_fin_k(float* __restrict__ S1, float* __restrict__ S2,
                           const float* __restrict__ cnt,
                           const float* __restrict__ gamma,
                           const float* __restrict__ beta,
                           const float* __restrict__ alpha) {
    int id = blockIdx.x * blockDim.x + threadIdx.x;  // G*HID
    int g = id >> 8, n = id & 255;
    float c = fmaxf(cnt[g], 1.f);
    float m = S1[id] / c;
    float eh2 = S2[id] / c;
    float a = alpha[n];
    float var = eh2 + m * m * (a * a - 2.f * a);
    float A = gamma[n] * rsqrtf(var + EPSF);
    float B = beta[n] - A * a * m;
    S1[id] = A; S2[id] = B;
}

__global__ void norm_apply_k(float* __restrict__ h, const int* __restrict__ batch,
                             const float* __restrict__ S1, const float* __restrict__ S2) {
    int id = blockIdx.x * blockDim.x + threadIdx.x;  // N_NODES*64
    int r = id >> 6, c4 = id & 63;
    int g = __ldg(batch + r);
    float4 a = ((const float4*)S1)[g * 64 + c4];
    float4 b = ((const float4*)S2)[g * 64 + c4];
    float4 v = ((const float4*)h)[id];
    v.x = a.x * v.x + b.x; v.y = a.y * v.y + b.y;
    v.z = a.z * v.z + b.z; v.w = a.w * v.w + b.w;
    ((float4*)h)[id] = v;
}

__global__ void pool_fin_k(const float* __restrict__ S1, const float* __restrict__ cnt,
                           float* __restrict__ pool) {
    int id = blockIdx.x * blockDim.x + threadIdx.x;  // G*HID
    int g = id >> 8;
    pool[id] = S1[id] / fmaxf(cnt[g], 1.f);
}

// ---------------- SGEMM: C = epi(A[M,256] @ W[256,256] + bias) --------------
// EPI: 0 plain, 1 relu, 2 edge struct-scale
#define BM 128
#define BN 128
#define BK 8
#define ASTR 132

template <int EPI>
__global__ __launch_bounds__(256, 2)
void gemm_k256(const float* __restrict__ A, const float* __restrict__ W,
               const float* __restrict__ bias, float* __restrict__ C, int M,
               const float* __restrict__ eattr, const float* __restrict__ sscale) {
    __shared__ float As[2][BK * ASTR];
    __shared__ float Bs[2][BK * BN];
    const int tid = threadIdx.x;
    const int bm = blockIdx.y * BM;
    const int bn = blockIdx.x * BN;

    const int arow = tid >> 1;          // 0..127
    const int acol = (tid & 1) * 4;     // 0 or 4
    const int brow = tid >> 5;          // 0..7
    const int bcol = (tid & 31) * 4;    // 0..124
    const int m0 = (tid >> 4) * 8;
    const int n0 = (tid & 15) * 8;

    float acc[8][8];
#pragma unroll
    for (int i = 0; i < 8; i++)
#pragma unroll
        for (int j = 0; j < 8; j++) acc[i][j] = 0.f;

    float4 aldg, bldg;
    {
        int r = bm + arow;
        aldg = (r < M) ? *(const float4*)(A + (long)r * HID + acol)
                       : make_float4(0, 0, 0, 0);
        bldg = *(const float4*)(W + (long)brow * HID + bn + bcol);
        As[0][(acol + 0) * ASTR + arow] = aldg.x;
        As[0][(acol + 1) * ASTR + arow] = aldg.y;
        As[0][(acol + 2) * ASTR + arow] = aldg.z;
        As[0][(acol + 3) * ASTR + arow] = aldg.w;
        *(float4*)(&Bs[0][brow * BN + bcol]) = bldg;
    }
    __syncthreads();

    const int NCH = HID / BK;  // 32
    for (int kc = 0; kc < NCH; kc++) {
        int buf = kc & 1;
        if (kc + 1 < NCH) {
            int k0 = (kc + 1) * BK;
            int r = bm + arow;
            aldg = (r < M) ? *(const float4*)(A + (long)r * HID + k0 + acol)
                           : make_float4(0, 0, 0, 0);
            bldg = *(const float4*)(W + (long)(k0 + brow) * HID + bn + bcol);
        }
#pragma unroll
        for (int kk = 0; kk < BK; kk++) {
            float a[8], b[8];
            *(float4*)(a)     = *(const float4*)(&As[buf][kk * ASTR + m0]);
            *(float4*)(a + 4) = *(const float4*)(&As[buf][kk * ASTR + m0 + 4]);
            *(float4*)(b)     = *(const float4*)(&Bs[buf][kk * BN + n0]);
            *(float4*)(b + 4) = *(const float4*)(&Bs[buf][kk * BN + n0 + 4]);
#pragma unroll
            for (int i = 0; i < 8; i++)
#pragma unroll
                for (int j = 0; j < 8; j++) acc[i][j] += a[i] * b[j];
        }
        if (kc + 1 < NCH) {
            int nb = buf ^ 1;
            As[nb][(acol + 0) * ASTR + arow] = aldg.x;
            As[nb][(acol + 1) * ASTR + arow] = aldg.y;
            As[nb][(acol + 2) * ASTR + arow] = aldg.z;
            As[nb][(acol + 3) * ASTR + arow] = aldg.w;
            *(float4*)(&Bs[nb][brow * BN + bcol]) = bldg;
        }
        __syncthreads();
    }

    float bsv[8];
    *(float4*)(bsv)     = *(const float4*)(bias + bn + n0);
    *(float4*)(bsv + 4) = *(const float4*)(bias + bn + n0 + 4);
    float ss = 1.f;
    if (EPI == 2) ss = *sscale;

#pragma unroll
    for (int i = 0; i < 8; i++) {
        int row = bm + m0 + i;
        if (row < M) {
            float scale = 1.f;
            if (EPI == 2) scale = (__ldg(eattr + (long)row * 4 + 1) > 0.f) ? ss : 1.f;
            float o[8];
#pragma unroll
            for (int j = 0; j < 8; j++) {
                float v = acc[i][j] + bsv[j];
                if (EPI == 1) v = fmaxf(v, 0.f);
                if (EPI == 2) v *= scale;
                o[j] = v;
            }
            *(float4*)(C + (long)row * HID + bn + n0)     = *(float4*)(o);
            *(float4*)(C + (long)row * HID + bn + n0 + 4) = *(float4*)(o + 4);
        }
    }
}

// ---------------- head: out[g] = relu(pool@W1t + bioC + b1) @ W2 + b2 -------
__global__ void head_k(const float* __restrict__ pool, const float* __restrict__ W1,
                       const float* __restrict__ b1, const float* __restrict__ bioC,
                       const float* __restrict__ W2, const float* __restrict__ b2,
                       float* __restrict__ out) {
    __shared__ float srow[HID];
    __shared__ float sred[256];
    int g = blockIdx.x, t = threadIdx.x;
    srow[t] = pool[g * HID + t];
    __syncthreads();
    float acc = bioC[t] + b1[t];
#pragma unroll 8
    for (int k = 0; k < HID; k++) acc += srow[k] * W1[k * HID + t];
    acc = fmaxf(acc, 0.f);
    sred[t] = acc * W2[t];
    __syncthreads();
    for (int s = 128; s > 0; s >>= 1) {
        if (t < s) sred[t] += sred[t + s];
        __syncthreads();
    }
    if (t == 0) out[g] = sred[0] + b2[0];
}

// ---------------- launch -----------------------------------------------------
static float* sym(const void* s) {
    void* p = nullptr;
    cudaGetSymbolAddress(&p, s);
    return (float*)p;
}

extern "C" void kernel_launch(void* const* d_in, const int* in_sizes, int n_in,
                              void* d_out, int out_size) {
    const int*   x     = (const int*)  d_in[0];
    const int*   ei    = (const int*)  d_in[1];
    const float* eattr = (const float*)d_in[2];
    const int*   batch = (const int*)  d_in[3];
    const float* nemb  = (const float*)d_in[4];
    const float* eeW   = (const float*)d_in[5];
    const float* eeb   = (const float*)d_in[6];
    const float* emW1  = (const float*)d_in[7];
    const float* emb1  = (const float*)d_in[8];
    const float* emW2  = (const float*)d_in[9];
    const float* emb2  = (const float*)d_in[10];
    const float* sscale= (const float*)d_in[11];
    const float* cW1   = (const float*)d_in[12];
    const float* cb1   = (const float*)d_in[13];
    const float* cW2   = (const float*)d_in[14];
    const float* cb2   = (const float*)d_in[15];
    const float* ceps  = (const float*)d_in[16];
    const float* gamma = (const float*)d_in[17];
    const float* beta  = (const float*)d_in[18];
    const float* alpha = (const float*)d_in[19];
    const float* bio   = (const float*)d_in[20];
    const float* hW1   = (const float*)d_in[21];
    const float* hb1   = (const float*)d_in[22];
    const float* hW2   = (const float*)d_in[23];
    const float* hb2   = (const float*)d_in[24];
    float* out = (float*)d_out;

    const int* src = ei;
    const int* dst = ei + N_EDGES;

    float *ph = sym(g_h), *pz = sym(g_z), *pt = sym(g_t);
    float *pe = sym(g_e), *pe1 = sym(g_e1);
    float *pWc = sym(g_Wc), *pbc = sym(g_bc), *pbio = sym(g_bioC);
    float *pcnt = sym(g_cnt), *pS1 = sym(g_S1), *pS2 = sym(g_S2);
    float *ppool = sym(g_pool);

    // precompute collapsed edge weights + bio constant
    prep_k<<<1, 256>>>(eeW, eeb, emW1, emb1, bio, hW1, pWc, pbc, pbio);

    // node counts per graph
    zero_f<<<1, 256>>>(pcnt, N_GRAPHS);
    count_k<<<(N_NODES + 255) / 256, 256>>>(batch, pcnt);

    // node embedding
    embed_k<<<(N_NODES * 64) / 256, 256>>>(x, nemb, ph);

    // edge features: e1 = relu(attr@Wc+bc); e = (e1@W2+b2)*struct_scale
    edge_k4<<<(N_EDGES * 64) / 256, 256>>>(eattr, pWc, pbc, pe1);
    gemm_k256<2><<<dim3(2, N_EDGES / BM), 256>>>(pe1, emW2, emb2, pe, N_EDGES,
                                                 eattr, sscale);

    const int gyN = (N_NODES + BM - 1) / BM;
    for (int l = 0; l < LAYERS; l++) {
        zinit_k<<<(N_NODES * 64) / 256, 256>>>(pz, ph, ceps, l);
        scatter_k<<<(N_EDGES * 64) / 256, 256>>>(pe, ph, pz, src, dst);
        gemm_k256<1><<<dim3(2, gyN), 256>>>(pz, cW1 + (long)l * HID * HID,
                                            cb1 + l * HID, pt, N_NODES,
                                            nullptr, nullptr);
        gemm_k256<0><<<dim3(2, gyN), 256>>>(pt, cW2 + (long)l * HID * HID,
                                            cb2 + l * HID, ph, N_NODES,
                                            nullptr, nullptr);
        // GraphNorm
        zero_f<<<256, 256>>>(pS1, N_GRAPHS * HID);
        zero_f<<<256, 256>>>(pS2, N_GRAPHS * HID);
        stats_k<<<((N_NODES / RPT) * 64 + 255) / 256, 256>>>(ph, batch, pS1, pS2);
        norm_fin_k<<<N_GRAPHS * HID / 256, 256>>>(pS1, pS2, pcnt,
                                                  gamma + l * HID, beta + l * HID,
                                                  alpha + l * HID);
        norm_apply_k<<<(N_NODES * 64) / 256, 256>>>(ph, batch, pS1, pS2);
    }

    // global mean pool
    zero_f<<<256, 256>>>(pS1, N_GRAPHS * HID);
    zero_f<<<256, 256>>>(pS2, N_GRAPHS * HID);
    stats_k<<<((N_NODES / RPT) * 64 + 255) / 256, 256>>>(ph, batch, pS1, pS2);
    pool_fin_k<<<N_GRAPHS * HID / 256, 256>>>(pS1, pcnt, ppool);

    // head
    head_k<<<N_GRAPHS, 256>>>(ppool, hW1, hb1, pbio, hW2, hb2, out);

    (void)in_sizes; (void)n_in; (void)out_size;
}